// round 12
// baseline (speedup 1.0000x reference)
#include <cuda_runtime.h>
#include <cstdint>

#define NN 50000
#define EE 800000
#define FIN 128
#define HID 100
#define CL 16
#define LEAKYS 0.01f
#define NB_SCAN 196   // ceil(NN/256)
#define GB 391        // gemm blocks = ceil(NN/128)

typedef unsigned long long ull;

// Scratch (alloc-free rule: __device__ globals). All fully rewritten each call.
__device__ int   g_cnt[NN];
__device__ int   g_off[NN];
__device__ int   g_cur[NN];
__device__ int   g_bsum[NB_SCAN];
__device__ float g_dinv[NN];
__device__ int   g_csrc[EE];
__device__ float g_Hs1[NN * HID];  // x@W1 (UNSCALED; dinv applied in gather1)
__device__ float g_Hs2[NN * CL];   // (leaky(out1)@W2) * dinv[row]

// ---------------- f32x2 helpers ----------------
__device__ __forceinline__ void fma2(ull& d, ull a, ull b) {
    asm("fma.rn.f32x2 %0, %1, %2, %0;" : "+l"(d) : "l"(a), "l"(b));
}
__device__ __forceinline__ ull packdup(float a) {
    ull r;
    asm("mov.b64 %0, {%1, %1};" : "=l"(r) : "f"(a));
    return r;
}
__device__ __forceinline__ void red_add_i32(int* p) {
    asm volatile("red.global.add.s32 [%0], 1;" :: "l"(p) : "memory");
}

// ---------------- Fused GEMM1 + per-thread degree histogram ----------------
// Every thread first fires ~8 REDG degree increments (no return value, drains in
// background), then runs the R6-proven f32x2 gemm. Hs1 = x @ W1 (no dinv).
__global__ __launch_bounds__(256) void k_gemm1_hist(const float* __restrict__ x,
                                                    const float* __restrict__ W1,
                                                    const int* __restrict__ ei) {
    __shared__ float As[2][16][128];  // [buf][k][m]
    __shared__ float Bs[2][16][128];  // [buf][k][n]
    int tid = threadIdx.x;

    // fire-and-forget histogram, grid-stride coalesced
    {
        const int* dsts = ei + EE;
        for (int e = blockIdx.x * 256 + tid; e < EE; e += GB * 256) {
            red_add_i32(&g_cnt[dsts[e]]);
        }
    }

    int tx = tid & 15, ty = tid >> 4;
    int m0 = blockIdx.x * 128;

    int mA = tid >> 1;
    int kA = (tid & 1) * 8;
    int rowA = m0 + mA;
    bool okA = rowA < NN;
    const float* xrow = x + (long)rowA * FIN + kA;

    float4 rA0, rA1;
    float rB[8];
    {
        rA0 = okA ? *(const float4*)(xrow + 0) : make_float4(0, 0, 0, 0);
        rA1 = okA ? *(const float4*)(xrow + 4) : make_float4(0, 0, 0, 0);
#pragma unroll
        for (int i = 0; i < 8; i++) {
            int idx = tid + i * 256;
            int k = idx >> 7, n = idx & 127;
            rB[i] = (n < HID) ? W1[k * HID + n] : 0.0f;
        }
        float av[8] = {rA0.x, rA0.y, rA0.z, rA0.w, rA1.x, rA1.y, rA1.z, rA1.w};
#pragma unroll
        for (int j = 0; j < 8; j++) As[0][kA + j][mA] = av[j];
#pragma unroll
        for (int i = 0; i < 8; i++) {
            int idx = tid + i * 256;
            Bs[0][idx >> 7][idx & 127] = rB[i];
        }
    }
    __syncthreads();

    ull acc[8][4];  // [mi][nj-pair]
#pragma unroll
    for (int i = 0; i < 8; i++)
#pragma unroll
        for (int j = 0; j < 4; j++) acc[i][j] = 0ull;

    for (int t = 0; t < 8; t++) {
        int buf = t & 1;
        if (t < 7) {
            int kk = (t + 1) * 16;
            rA0 = okA ? *(const float4*)(xrow + kk + 0) : make_float4(0, 0, 0, 0);
            rA1 = okA ? *(const float4*)(xrow + kk + 4) : make_float4(0, 0, 0, 0);
#pragma unroll
            for (int i = 0; i < 8; i++) {
                int idx = tid + i * 256;
                int k = idx >> 7, n = idx & 127;
                rB[i] = (n < HID) ? W1[(kk + k) * HID + n] : 0.0f;
            }
        }
#pragma unroll
        for (int k = 0; k < 16; k++) {
            float4 a0 = *(const float4*)&As[buf][k][ty * 8];
            float4 a1 = *(const float4*)&As[buf][k][ty * 8 + 4];
            const ull* bp = (const ull*)&Bs[buf][k][tx * 8];
            ull b2[4] = {bp[0], bp[1], bp[2], bp[3]};
            float a[8] = {a0.x, a0.y, a0.z, a0.w, a1.x, a1.y, a1.z, a1.w};
#pragma unroll
            for (int i = 0; i < 8; i++) {
                ull a2 = packdup(a[i]);
#pragma unroll
                for (int j = 0; j < 4; j++) fma2(acc[i][j], a2, b2[j]);
            }
        }
        if (t < 7) {
            int nb = buf ^ 1;
            float av[8] = {rA0.x, rA0.y, rA0.z, rA0.w, rA1.x, rA1.y, rA1.z, rA1.w};
#pragma unroll
            for (int j = 0; j < 8; j++) As[nb][kA + j][mA] = av[j];
#pragma unroll
            for (int i = 0; i < 8; i++) {
                int idx = tid + i * 256;
                Bs[nb][idx >> 7][idx & 127] = rB[i];
            }
            __syncthreads();
        }
    }

#pragma unroll
    for (int i = 0; i < 8; i++) {
        int row = m0 + ty * 8 + i;
        if (row >= NN) continue;
#pragma unroll
        for (int j = 0; j < 4; j++) {
            int col = tx * 8 + j * 2;
            if (col < HID) {
                float lo, hi;
                asm("mov.b64 {%0, %1}, %2;" : "=f"(lo), "=f"(hi) : "l"(acc[i][j]));
                *(float2*)(g_Hs1 + (long)row * HID + col) = make_float2(lo, hi);
            }
        }
    }
}

// ---------------- CSR scan/place ----------------
__global__ void k_scanA() {
    __shared__ int s[256];
    int tid = threadIdx.x;
    int i = blockIdx.x * 256 + tid;
    int val = (i < NN) ? g_cnt[i] : 0;
    if (i < NN) g_dinv[i] = rsqrtf((float)val + 1.0f);
    s[tid] = val;
    __syncthreads();
#pragma unroll
    for (int off = 1; off < 256; off <<= 1) {
        int t = (tid >= off) ? s[tid - off] : 0;
        __syncthreads();
        s[tid] += t;
        __syncthreads();
    }
    if (i < NN) g_off[i] = s[tid] - val;
    if (tid == 255) g_bsum[blockIdx.x] = s[255];
}
__global__ void k_scanC() {
    __shared__ int red[256];
    int tid = threadIdx.x;
    int bid = blockIdx.x;
    int v = (tid < bid) ? g_bsum[tid] : 0;   // NB_SCAN <= 256
    red[tid] = v;
    __syncthreads();
#pragma unroll
    for (int off = 128; off >= 1; off >>= 1) {
        if (tid < off) red[tid] += red[tid + off];
        __syncthreads();
    }
    int base = red[0];
    int i = bid * 256 + tid;
    if (i < NN) {
        int o = g_off[i] + base;
        g_off[i] = o;
        g_cur[i] = o;
    }
}
__global__ void k_place(const int* __restrict__ ei) {
    int e = blockIdx.x * blockDim.x + threadIdx.x;
    if (e < EE) {
        int d = ei[EE + e];
        int pos = atomicAdd(&g_cur[d], 1);
        g_csrc[pos] = ei[e];
    }
}

// ---------------- Gather layer 1 (+dinv[s] scaling) + leaky + fused GEMM2 ----------------
__global__ __launch_bounds__(256) void k_gather1(const float* __restrict__ b1,
                                                 const float* __restrict__ W2,
                                                 const float* __restrict__ b2,
                                                 float* __restrict__ out) {
    __shared__ float W2s[HID][17];
    __shared__ float b1s[HID];
    __shared__ float b2s[CL];
    __shared__ float us[8][HID];
    int tid = threadIdx.x;
    for (int i = tid; i < HID * CL; i += 256) W2s[i / CL][i % CL] = W2[i];
    for (int i = tid; i < HID; i += 256) b1s[i] = b1[i];
    if (tid < CL) b2s[tid] = b2[tid];
    __syncthreads();

    int wid = tid >> 5, lane = tid & 31;
    int node = blockIdx.x * 8 + wid;
    if (node >= NN) return;

    int c0 = lane, c1 = lane + 32, c2 = lane + 64, c3 = lane + 96;
    bool has3 = c3 < HID;
    float di = g_dinv[node];
    const float* selfrow = g_Hs1 + (long)node * HID;
    float a0 = di * selfrow[c0];
    float a1 = di * selfrow[c1];
    float a2 = di * selfrow[c2];
    float a3 = has3 ? di * selfrow[c3] : 0.0f;

    int start = g_off[node];
    int end = start + g_cnt[node];
    for (int j = start; j < end; j++) {
        int s = g_csrc[j];
        float ds = g_dinv[s];
        const float* r = g_Hs1 + (long)s * HID;
        a0 += ds * r[c0];
        a1 += ds * r[c1];
        a2 += ds * r[c2];
        if (has3) a3 += ds * r[c3];
    }

    float o0 = b1s[c0] + di * a0;
    float o1 = b1s[c1] + di * a1;
    float o2 = b1s[c2] + di * a2;
    us[wid][c0] = o0 > 0.f ? o0 : LEAKYS * o0;
    us[wid][c1] = o1 > 0.f ? o1 : LEAKYS * o1;
    us[wid][c2] = o2 > 0.f ? o2 : LEAKYS * o2;
    if (has3) {
        float o3 = b1s[c3] + di * a3;
        us[wid][c3] = o3 > 0.f ? o3 : LEAKYS * o3;
    }
    __syncwarp();

    int c = lane & 15;
    int k0 = (lane >> 4) * 50;
    float p = 0.0f;
#pragma unroll 5
    for (int k = 0; k < 50; k++) {
        p += us[wid][k0 + k] * W2s[k0 + k][c];
    }
    p += __shfl_xor_sync(0xffffffffu, p, 16);
    if (lane < 16) {
        float h2 = di * p;
        g_Hs2[(long)node * CL + c] = h2;
        out[(long)node * CL + c] = b2s[c] + h2 * di;
    }
}

// ---------------- Gather layer 2 + log_softmax ----------------
__global__ __launch_bounds__(256) void k_gather2(float* __restrict__ out) {
    int t = blockIdx.x * 256 + threadIdx.x;
    int node = t >> 4;
    int c = t & 15;
    if (node >= NN) return;

    int start = g_off[node];
    int end = start + g_cnt[node];
    float acc = 0.0f;
    for (int j = start; j < end; j++) {
        int s = g_csrc[j];
        acc += g_Hs2[(long)s * CL + c];
    }
    float v = out[(long)node * CL + c] + g_dinv[node] * acc;

    float m = v;
#pragma unroll
    for (int msk = 8; msk >= 1; msk >>= 1)
        m = fmaxf(m, __shfl_xor_sync(0xffffffffu, m, msk, 16));
    float e = expf(v - m);
#pragma unroll
    for (int msk = 8; msk >= 1; msk >>= 1)
        e += __shfl_xor_sync(0xffffffffu, e, msk, 16);
    out[(long)node * CL + c] = v - m - logf(e);
}

extern "C" void kernel_launch(void* const* d_in, const int* in_sizes, int n_in,
                              void* d_out, int out_size) {
    const float* x  = (const float*)d_in[0];
    const float* W1 = (const float*)d_in[1];
    const float* b1 = (const float*)d_in[2];
    const float* W2 = (const float*)d_in[3];
    const float* b2 = (const float*)d_in[4];
    const int*   ei = (const int*)d_in[5];
    float* out = (float*)d_out;

    // zero g_cnt via async memset (graph-capturable, no alloc)
    void* cnt_ptr = nullptr;
    cudaGetSymbolAddress(&cnt_ptr, g_cnt);
    cudaMemsetAsync(cnt_ptr, 0, NN * sizeof(int));

    k_gemm1_hist<<<GB, 256>>>(x, W1, ei);
    k_scanA<<<NB_SCAN, 256>>>();
    k_scanC<<<NB_SCAN, 256>>>();
    k_place<<<(EE + 255) / 256, 256>>>(ei);
    k_gather1<<<(NN + 7) / 8, 256>>>(b1, W2, b2, out);
    k_gather2<<<(NN * 16 + 255) / 256, 256>>>(out);
}

// round 13
// speedup vs baseline: 1.4844x; 1.4844x over previous
#include <cuda_runtime.h>
#include <cstdint>

#define NN 50000
#define EE 800000
#define FIN 128
#define HID 100
#define CL 16
#define LEAKYS 0.01f
#define NB_SCAN 196   // ceil(NN/256)

typedef unsigned long long ull;

// Scratch (alloc-free rule: __device__ globals). All fully rewritten each call.
__device__ int   g_cnt[NN];
__device__ int   g_off[NN];
__device__ int   g_cur[NN];
__device__ int   g_bsum[NB_SCAN];
__device__ float g_dinv[NN];
__device__ int   g_csrc[EE];
__device__ float g_Hs1[NN * HID];  // (x@W1) * dinv[row]
__device__ float g_Hs2[NN * CL];   // (leaky(out1)@W2) * dinv[row]

// ---------------- CSR build ----------------
__global__ void k_hist(const int* __restrict__ ei) {
    int e = blockIdx.x * blockDim.x + threadIdx.x;
    if (e < EE) atomicAdd(&g_cnt[ei[EE + e]], 1);
}
__global__ void k_scanA() {
    __shared__ int s[256];
    int tid = threadIdx.x;
    int i = blockIdx.x * 256 + tid;
    int val = (i < NN) ? g_cnt[i] : 0;
    if (i < NN) g_dinv[i] = rsqrtf((float)val + 1.0f);
    s[tid] = val;
    __syncthreads();
#pragma unroll
    for (int off = 1; off < 256; off <<= 1) {
        int t = (tid >= off) ? s[tid - off] : 0;
        __syncthreads();
        s[tid] += t;
        __syncthreads();
    }
    if (i < NN) g_off[i] = s[tid] - val;
    if (tid == 255) g_bsum[blockIdx.x] = s[255];
}
__global__ void k_scanC() {
    __shared__ int red[256];
    int tid = threadIdx.x;
    int bid = blockIdx.x;
    int v = (tid < bid) ? g_bsum[tid] : 0;   // NB_SCAN <= 256
    red[tid] = v;
    __syncthreads();
#pragma unroll
    for (int off = 128; off >= 1; off >>= 1) {
        if (tid < off) red[tid] += red[tid + off];
        __syncthreads();
    }
    int base = red[0];
    int i = bid * 256 + tid;
    if (i < NN) {
        int o = g_off[i] + base;
        g_off[i] = o;
        g_cur[i] = o;
    }
}
__global__ void k_place(const int* __restrict__ ei) {
    int e = blockIdx.x * blockDim.x + threadIdx.x;
    if (e < EE) {
        int d = ei[EE + e];
        int pos = atomicAdd(&g_cur[d], 1);
        g_csrc[pos] = ei[e];
    }
}

// ---------------- GEMM1 (SIMT, packed f32x2 FMA) — R6-proven version ----------------
__device__ __forceinline__ void fma2(ull& d, ull a, ull b) {
    asm("fma.rn.f32x2 %0, %1, %2, %0;" : "+l"(d) : "l"(a), "l"(b));
}
__device__ __forceinline__ ull packdup(float a) {
    ull r;
    asm("mov.b64 %0, {%1, %1};" : "=l"(r) : "f"(a));
    return r;
}

__global__ __launch_bounds__(256) void k_gemm1(const float* __restrict__ x,
                                               const float* __restrict__ W1) {
    __shared__ float As[2][16][128];  // [buf][k][m]
    __shared__ float Bs[2][16][128];  // [buf][k][n]
    int tid = threadIdx.x;
    int tx = tid & 15, ty = tid >> 4;
    int m0 = blockIdx.x * 128;

    int mA = tid >> 1;
    int kA = (tid & 1) * 8;
    int rowA = m0 + mA;
    bool okA = rowA < NN;
    const float* xrow = x + (long)rowA * FIN + kA;

    float4 rA0, rA1;
    float rB[8];
    {
        rA0 = okA ? *(const float4*)(xrow + 0) : make_float4(0, 0, 0, 0);
        rA1 = okA ? *(const float4*)(xrow + 4) : make_float4(0, 0, 0, 0);
#pragma unroll
        for (int i = 0; i < 8; i++) {
            int idx = tid + i * 256;
            int k = idx >> 7, n = idx & 127;
            rB[i] = (n < HID) ? W1[k * HID + n] : 0.0f;
        }
        float av[8] = {rA0.x, rA0.y, rA0.z, rA0.w, rA1.x, rA1.y, rA1.z, rA1.w};
#pragma unroll
        for (int j = 0; j < 8; j++) As[0][kA + j][mA] = av[j];
#pragma unroll
        for (int i = 0; i < 8; i++) {
            int idx = tid + i * 256;
            Bs[0][idx >> 7][idx & 127] = rB[i];
        }
    }
    __syncthreads();

    ull acc[8][4];  // [mi][nj-pair]
#pragma unroll
    for (int i = 0; i < 8; i++)
#pragma unroll
        for (int j = 0; j < 4; j++) acc[i][j] = 0ull;

    for (int t = 0; t < 8; t++) {
        int buf = t & 1;
        if (t < 7) {
            int kk = (t + 1) * 16;
            rA0 = okA ? *(const float4*)(xrow + kk + 0) : make_float4(0, 0, 0, 0);
            rA1 = okA ? *(const float4*)(xrow + kk + 4) : make_float4(0, 0, 0, 0);
#pragma unroll
            for (int i = 0; i < 8; i++) {
                int idx = tid + i * 256;
                int k = idx >> 7, n = idx & 127;
                rB[i] = (n < HID) ? W1[(kk + k) * HID + n] : 0.0f;
            }
        }
#pragma unroll
        for (int k = 0; k < 16; k++) {
            float4 a0 = *(const float4*)&As[buf][k][ty * 8];
            float4 a1 = *(const float4*)&As[buf][k][ty * 8 + 4];
            const ull* bp = (const ull*)&Bs[buf][k][tx * 8];
            ull b2[4] = {bp[0], bp[1], bp[2], bp[3]};
            float a[8] = {a0.x, a0.y, a0.z, a0.w, a1.x, a1.y, a1.z, a1.w};
#pragma unroll
            for (int i = 0; i < 8; i++) {
                ull a2 = packdup(a[i]);
#pragma unroll
                for (int j = 0; j < 4; j++) fma2(acc[i][j], a2, b2[j]);
            }
        }
        if (t < 7) {
            int nb = buf ^ 1;
            float av[8] = {rA0.x, rA0.y, rA0.z, rA0.w, rA1.x, rA1.y, rA1.z, rA1.w};
#pragma unroll
            for (int j = 0; j < 8; j++) As[nb][kA + j][mA] = av[j];
#pragma unroll
            for (int i = 0; i < 8; i++) {
                int idx = tid + i * 256;
                Bs[nb][idx >> 7][idx & 127] = rB[i];
            }
            __syncthreads();
        }
    }

#pragma unroll
    for (int i = 0; i < 8; i++) {
        int row = m0 + ty * 8 + i;
        if (row >= NN) continue;
        float di = g_dinv[row];
#pragma unroll
        for (int j = 0; j < 4; j++) {
            int col = tx * 8 + j * 2;
            if (col < HID) {
                float lo, hi;
                asm("mov.b64 {%0, %1}, %2;" : "=f"(lo), "=f"(hi) : "l"(acc[i][j]));
                *(float2*)(g_Hs1 + (long)row * HID + col) =
                    make_float2(lo * di, hi * di);
            }
        }
    }
}

// ---------------- Gather layer 1 + leaky + fused GEMM2 (index prefetch) ----------------
__global__ __launch_bounds__(256) void k_gather1(const float* __restrict__ b1,
                                                 const float* __restrict__ W2,
                                                 const float* __restrict__ b2,
                                                 float* __restrict__ out) {
    __shared__ float W2s[HID][17];
    __shared__ float b1s[HID];
    __shared__ float b2s[CL];
    __shared__ float us[8][HID];
    int tid = threadIdx.x;
    for (int i = tid; i < HID * CL; i += 256) W2s[i / CL][i % CL] = W2[i];
    for (int i = tid; i < HID; i += 256) b1s[i] = b1[i];
    if (tid < CL) b2s[tid] = b2[tid];
    __syncthreads();

    int wid = tid >> 5, lane = tid & 31;
    int node = blockIdx.x * 8 + wid;
    if (node >= NN) return;

    int c0 = lane, c1 = lane + 32, c2 = lane + 64, c3 = lane + 96;
    bool has3 = c3 < HID;
    const float* selfrow = g_Hs1 + (long)node * HID;
    float a0 = selfrow[c0];
    float a1 = selfrow[c1];
    float a2 = selfrow[c2];
    float a3 = has3 ? selfrow[c3] : 0.0f;

    int start = g_off[node];
    int end = start + g_cnt[node];
    int s_next = (start < end) ? g_csrc[start] : 0;
    for (int j = start; j < end; j++) {
        int s = s_next;
        if (j + 1 < end) s_next = g_csrc[j + 1];  // prefetch next index
        const float* r = g_Hs1 + (long)s * HID;
        a0 += r[c0];
        a1 += r[c1];
        a2 += r[c2];
        if (has3) a3 += r[c3];
    }

    float di = g_dinv[node];
    float o0 = b1s[c0] + di * a0;
    float o1 = b1s[c1] + di * a1;
    float o2 = b1s[c2] + di * a2;
    us[wid][c0] = o0 > 0.f ? o0 : LEAKYS * o0;
    us[wid][c1] = o1 > 0.f ? o1 : LEAKYS * o1;
    us[wid][c2] = o2 > 0.f ? o2 : LEAKYS * o2;
    if (has3) {
        float o3 = b1s[c3] + di * a3;
        us[wid][c3] = o3 > 0.f ? o3 : LEAKYS * o3;
    }
    __syncwarp();

    int c = lane & 15;
    int k0 = (lane >> 4) * 50;
    float p = 0.0f;
#pragma unroll 5
    for (int k = 0; k < 50; k++) {
        p += us[wid][k0 + k] * W2s[k0 + k][c];
    }
    p += __shfl_xor_sync(0xffffffffu, p, 16);
    if (lane < 16) {
        float h2 = di * p;
        g_Hs2[(long)node * CL + c] = h2;
        out[(long)node * CL + c] = b2s[c] + h2 * di;
    }
}

// ---------------- Gather layer 2 + log_softmax (index prefetch) ----------------
__global__ __launch_bounds__(256) void k_gather2(float* __restrict__ out) {
    int t = blockIdx.x * 256 + threadIdx.x;
    int node = t >> 4;
    int c = t & 15;
    if (node >= NN) return;

    int start = g_off[node];
    int end = start + g_cnt[node];
    float acc = 0.0f;
    int s_next = (start < end) ? g_csrc[start] : 0;
    for (int j = start; j < end; j++) {
        int s = s_next;
        if (j + 1 < end) s_next = g_csrc[j + 1];
        acc += g_Hs2[(long)s * CL + c];
    }
    float v = out[(long)node * CL + c] + g_dinv[node] * acc;

    float m = v;
#pragma unroll
    for (int msk = 8; msk >= 1; msk >>= 1)
        m = fmaxf(m, __shfl_xor_sync(0xffffffffu, m, msk, 16));
    float e = expf(v - m);
#pragma unroll
    for (int msk = 8; msk >= 1; msk >>= 1)
        e += __shfl_xor_sync(0xffffffffu, e, msk, 16);
    out[(long)node * CL + c] = v - m - logf(e);
}

extern "C" void kernel_launch(void* const* d_in, const int* in_sizes, int n_in,
                              void* d_out, int out_size) {
    const float* x  = (const float*)d_in[0];
    const float* W1 = (const float*)d_in[1];
    const float* b1 = (const float*)d_in[2];
    const float* W2 = (const float*)d_in[3];
    const float* b2 = (const float*)d_in[4];
    const int*   ei = (const int*)d_in[5];
    float* out = (float*)d_out;

    // zero g_cnt via async memset (graph-capturable, no alloc)
    void* cnt_ptr = nullptr;
    cudaGetSymbolAddress(&cnt_ptr, g_cnt);
    cudaMemsetAsync(cnt_ptr, 0, NN * sizeof(int));

    k_hist<<<(EE + 255) / 256, 256>>>(ei);
    k_scanA<<<NB_SCAN, 256>>>();
    k_scanC<<<NB_SCAN, 256>>>();
    k_place<<<(EE + 255) / 256, 256>>>(ei);
    k_gemm1<<<(NN + 127) / 128, 256>>>(x, W1);
    k_gather1<<<(NN + 7) / 8, 256>>>(b1, W2, b2, out);
    k_gather2<<<(NN * 16 + 255) / 256, 256>>>(out);
}

// round 14
// speedup vs baseline: 1.6335x; 1.1004x over previous
#include <cuda_runtime.h>
#include <cstdint>

#define NN 50000
#define EE 800000
#define FIN 128
#define HID 100
#define CL 16
#define LEAKYS 0.01f
#define NB_SCAN 196   // ceil(NN/256)

typedef unsigned long long ull;

// Scratch (alloc-free rule: __device__ globals). All fully rewritten each call.
__device__ int   g_cnt[NN];
__device__ int   g_off[NN];
__device__ int   g_cur[NN];
__device__ int   g_bsum[NB_SCAN];
__device__ float g_dinv[NN];
__device__ int   g_csrc[EE];
__device__ float g_Hs1[NN * HID];  // x@W1 (UNSCALED; dinv applied in gather1)
__device__ float g_Hs2[NN * CL];   // (leaky(out1)@W2) * dinv[row]

// ---------------- CSR build ----------------
__global__ void k_hist(const int* __restrict__ ei) {
    int e = blockIdx.x * blockDim.x + threadIdx.x;
    if (e < EE) atomicAdd(&g_cnt[ei[EE + e]], 1);
}
__global__ void k_scanA() {
    __shared__ int s[256];
    int tid = threadIdx.x;
    int i = blockIdx.x * 256 + tid;
    int val = (i < NN) ? g_cnt[i] : 0;
    if (i < NN) g_dinv[i] = rsqrtf((float)val + 1.0f);
    s[tid] = val;
    __syncthreads();
#pragma unroll
    for (int off = 1; off < 256; off <<= 1) {
        int t = (tid >= off) ? s[tid - off] : 0;
        __syncthreads();
        s[tid] += t;
        __syncthreads();
    }
    if (i < NN) g_off[i] = s[tid] - val;
    if (tid == 255) g_bsum[blockIdx.x] = s[255];
}
__global__ void k_scanC() {
    __shared__ int red[256];
    int tid = threadIdx.x;
    int bid = blockIdx.x;
    int v = (tid < bid) ? g_bsum[tid] : 0;   // NB_SCAN <= 256
    red[tid] = v;
    __syncthreads();
#pragma unroll
    for (int off = 128; off >= 1; off >>= 1) {
        if (tid < off) red[tid] += red[tid + off];
        __syncthreads();
    }
    int base = red[0];
    int i = bid * 256 + tid;
    if (i < NN) {
        int o = g_off[i] + base;
        g_off[i] = o;
        g_cur[i] = o;
    }
}
__global__ void k_place(const int* __restrict__ ei) {
    int e = blockIdx.x * blockDim.x + threadIdx.x;
    if (e < EE) {
        int d = ei[EE + e];
        int pos = atomicAdd(&g_cur[d], 1);
        g_csrc[pos] = ei[e];
    }
}

// ---------------- GEMM1 (SIMT, packed f32x2 FMA) — R6-proven, UNSCALED output ----------------
__device__ __forceinline__ void fma2(ull& d, ull a, ull b) {
    asm("fma.rn.f32x2 %0, %1, %2, %0;" : "+l"(d) : "l"(a), "l"(b));
}
__device__ __forceinline__ ull packdup(float a) {
    ull r;
    asm("mov.b64 %0, {%1, %1};" : "=l"(r) : "f"(a));
    return r;
}

__global__ __launch_bounds__(256) void k_gemm1(const float* __restrict__ x,
                                               const float* __restrict__ W1) {
    __shared__ float As[2][16][128];  // [buf][k][m]
    __shared__ float Bs[2][16][128];  // [buf][k][n]
    int tid = threadIdx.x;
    int tx = tid & 15, ty = tid >> 4;
    int m0 = blockIdx.x * 128;

    int mA = tid >> 1;
    int kA = (tid & 1) * 8;
    int rowA = m0 + mA;
    bool okA = rowA < NN;
    const float* xrow = x + (long)rowA * FIN + kA;

    float4 rA0, rA1;
    float rB[8];
    {
        rA0 = okA ? *(const float4*)(xrow + 0) : make_float4(0, 0, 0, 0);
        rA1 = okA ? *(const float4*)(xrow + 4) : make_float4(0, 0, 0, 0);
#pragma unroll
        for (int i = 0; i < 8; i++) {
            int idx = tid + i * 256;
            int k = idx >> 7, n = idx & 127;
            rB[i] = (n < HID) ? W1[k * HID + n] : 0.0f;
        }
        float av[8] = {rA0.x, rA0.y, rA0.z, rA0.w, rA1.x, rA1.y, rA1.z, rA1.w};
#pragma unroll
        for (int j = 0; j < 8; j++) As[0][kA + j][mA] = av[j];
#pragma unroll
        for (int i = 0; i < 8; i++) {
            int idx = tid + i * 256;
            Bs[0][idx >> 7][idx & 127] = rB[i];
        }
    }
    __syncthreads();

    ull acc[8][4];  // [mi][nj-pair]
#pragma unroll
    for (int i = 0; i < 8; i++)
#pragma unroll
        for (int j = 0; j < 4; j++) acc[i][j] = 0ull;

    for (int t = 0; t < 8; t++) {
        int buf = t & 1;
        if (t < 7) {
            int kk = (t + 1) * 16;
            rA0 = okA ? *(const float4*)(xrow + kk + 0) : make_float4(0, 0, 0, 0);
            rA1 = okA ? *(const float4*)(xrow + kk + 4) : make_float4(0, 0, 0, 0);
#pragma unroll
            for (int i = 0; i < 8; i++) {
                int idx = tid + i * 256;
                int k = idx >> 7, n = idx & 127;
                rB[i] = (n < HID) ? W1[(kk + k) * HID + n] : 0.0f;
            }
        }
#pragma unroll
        for (int k = 0; k < 16; k++) {
            float4 a0 = *(const float4*)&As[buf][k][ty * 8];
            float4 a1 = *(const float4*)&As[buf][k][ty * 8 + 4];
            const ull* bp = (const ull*)&Bs[buf][k][tx * 8];
            ull b2[4] = {bp[0], bp[1], bp[2], bp[3]};
            float a[8] = {a0.x, a0.y, a0.z, a0.w, a1.x, a1.y, a1.z, a1.w};
#pragma unroll
            for (int i = 0; i < 8; i++) {
                ull a2 = packdup(a[i]);
#pragma unroll
                for (int j = 0; j < 4; j++) fma2(acc[i][j], a2, b2[j]);
            }
        }
        if (t < 7) {
            int nb = buf ^ 1;
            float av[8] = {rA0.x, rA0.y, rA0.z, rA0.w, rA1.x, rA1.y, rA1.z, rA1.w};
#pragma unroll
            for (int j = 0; j < 8; j++) As[nb][kA + j][mA] = av[j];
#pragma unroll
            for (int i = 0; i < 8; i++) {
                int idx = tid + i * 256;
                Bs[nb][idx >> 7][idx & 127] = rB[i];
            }
            __syncthreads();
        }
    }

#pragma unroll
    for (int i = 0; i < 8; i++) {
        int row = m0 + ty * 8 + i;
        if (row >= NN) continue;
#pragma unroll
        for (int j = 0; j < 4; j++) {
            int col = tx * 8 + j * 2;
            if (col < HID) {
                float lo, hi;
                asm("mov.b64 {%0, %1}, %2;" : "=f"(lo), "=f"(hi) : "l"(acc[i][j]));
                *(float2*)(g_Hs1 + (long)row * HID + col) = make_float2(lo, hi);
            }
        }
    }
}

// ---------------- Gather layer 1 (+dinv[s] scaling) + leaky + fused GEMM2 ----------------
__global__ __launch_bounds__(256) void k_gather1(const float* __restrict__ b1,
                                                 const float* __restrict__ W2,
                                                 const float* __restrict__ b2,
                                                 float* __restrict__ out) {
    __shared__ float W2s[HID][17];
    __shared__ float b1s[HID];
    __shared__ float b2s[CL];
    __shared__ float us[8][HID];
    int tid = threadIdx.x;
    for (int i = tid; i < HID * CL; i += 256) W2s[i / CL][i % CL] = W2[i];
    for (int i = tid; i < HID; i += 256) b1s[i] = b1[i];
    if (tid < CL) b2s[tid] = b2[tid];
    __syncthreads();

    int wid = tid >> 5, lane = tid & 31;
    int node = blockIdx.x * 8 + wid;
    if (node >= NN) return;

    int c0 = lane, c1 = lane + 32, c2 = lane + 64, c3 = lane + 96;
    bool has3 = c3 < HID;
    float di = g_dinv[node];
    const float* selfrow = g_Hs1 + (long)node * HID;
    float a0 = di * selfrow[c0];
    float a1 = di * selfrow[c1];
    float a2 = di * selfrow[c2];
    float a3 = has3 ? di * selfrow[c3] : 0.0f;

    int start = g_off[node];
    int end = start + g_cnt[node];
    for (int j = start; j < end; j++) {
        int s = g_csrc[j];
        float ds = g_dinv[s];
        const float* r = g_Hs1 + (long)s * HID;
        a0 += ds * r[c0];
        a1 += ds * r[c1];
        a2 += ds * r[c2];
        if (has3) a3 += ds * r[c3];
    }

    float o0 = b1s[c0] + di * a0;
    float o1 = b1s[c1] + di * a1;
    float o2 = b1s[c2] + di * a2;
    us[wid][c0] = o0 > 0.f ? o0 : LEAKYS * o0;
    us[wid][c1] = o1 > 0.f ? o1 : LEAKYS * o1;
    us[wid][c2] = o2 > 0.f ? o2 : LEAKYS * o2;
    if (has3) {
        float o3 = b1s[c3] + di * a3;
        us[wid][c3] = o3 > 0.f ? o3 : LEAKYS * o3;
    }
    __syncwarp();

    int c = lane & 15;
    int k0 = (lane >> 4) * 50;
    float p = 0.0f;
#pragma unroll 5
    for (int k = 0; k < 50; k++) {
        p += us[wid][k0 + k] * W2s[k0 + k][c];
    }
    p += __shfl_xor_sync(0xffffffffu, p, 16);
    if (lane < 16) {
        float h2 = di * p;
        g_Hs2[(long)node * CL + c] = h2;
        out[(long)node * CL + c] = b2s[c] + h2 * di;
    }
}

// ---------------- Gather layer 2 + log_softmax ----------------
__global__ __launch_bounds__(256) void k_gather2(float* __restrict__ out) {
    int t = blockIdx.x * 256 + threadIdx.x;
    int node = t >> 4;
    int c = t & 15;
    if (node >= NN) return;

    int start = g_off[node];
    int end = start + g_cnt[node];
    float acc = 0.0f;
    for (int j = start; j < end; j++) {
        int s = g_csrc[j];
        acc += g_Hs2[(long)s * CL + c];
    }
    float v = out[(long)node * CL + c] + g_dinv[node] * acc;

    float m = v;
#pragma unroll
    for (int msk = 8; msk >= 1; msk >>= 1)
        m = fmaxf(m, __shfl_xor_sync(0xffffffffu, m, msk, 16));
    float e = expf(v - m);
#pragma unroll
    for (int msk = 8; msk >= 1; msk >>= 1)
        e += __shfl_xor_sync(0xffffffffu, e, msk, 16);
    out[(long)node * CL + c] = v - m - logf(e);
}

extern "C" void kernel_launch(void* const* d_in, const int* in_sizes, int n_in,
                              void* d_out, int out_size) {
    const float* x  = (const float*)d_in[0];
    const float* W1 = (const float*)d_in[1];
    const float* b1 = (const float*)d_in[2];
    const float* W2 = (const float*)d_in[3];
    const float* b2 = (const float*)d_in[4];
    const int*   ei = (const int*)d_in[5];
    float* out = (float*)d_out;

    // One-time handle creation (first call = correctness run, NOT under capture).
    // Handles only — identical work is issued on every call.
    static cudaStream_t s2 = nullptr;
    static cudaEvent_t evFork = nullptr, evJoin = nullptr;
    if (s2 == nullptr) {
        cudaStreamCreateWithFlags(&s2, cudaStreamNonBlocking);
        cudaEventCreateWithFlags(&evFork, cudaEventDisableTiming);
        cudaEventCreateWithFlags(&evJoin, cudaEventDisableTiming);
    }

    // Fork: gemm1 (independent of CSR build) runs on s2.
    cudaEventRecord(evFork, 0);
    cudaStreamWaitEvent(s2, evFork, 0);
    k_gemm1<<<(NN + 127) / 128, 256, 0, s2>>>(x, W1);
    cudaEventRecord(evJoin, s2);

    // Main branch: CSR build.
    void* cnt_ptr = nullptr;
    cudaGetSymbolAddress(&cnt_ptr, g_cnt);
    cudaMemsetAsync(cnt_ptr, 0, NN * sizeof(int));
    k_hist<<<(EE + 255) / 256, 256>>>(ei);
    k_scanA<<<NB_SCAN, 256>>>();
    k_scanC<<<NB_SCAN, 256>>>();
    k_place<<<(EE + 255) / 256, 256>>>(ei);

    // Join, then the dependent tail.
    cudaStreamWaitEvent(0, evJoin, 0);
    k_gather1<<<(NN + 7) / 8, 256>>>(b1, W2, b2, out);
    k_gather2<<<(NN * 16 + 255) / 256, 256>>>(out);
}